// round 14
// baseline (speedup 1.0000x reference)
#include <cuda_runtime.h>

typedef unsigned long long ull;

#define B_  4
#define N_  1024
#define F_  128
#define R_  16
#define E_  65536
#define BN_ 4096

// ---------------- device scratch ----------------
__device__ __align__(16) float g_agg1[2][BN_][F_];
__device__ __align__(16) float g_h[2][BN_][F_];
__device__ __align__(16) float g_Shat[(size_t)B_ * N_ * N_];
__device__ float g_rowmax[BN_];
__device__ float g_rowinv[BN_];
__device__ __align__(16) float g_rt[BN_ * R_];
__device__ __align__(16) float g_agg2S[2][BN_ * R_];   // s-side agg, per step
__device__ __align__(16) float g_agg2t[BN_ * R_];      // t-side agg, reused per step
__device__ __align__(16) float g_a2[2][BN_ * R_];      // s-side folded output, per step
__device__ __align__(16) float g_c[BN_ * R_];

// ---------------- helpers ----------------
__device__ __forceinline__ void red_add_v4(float* p, float4 v) {
    ull gp = (ull)__cvta_generic_to_global(p);
    asm volatile("red.global.add.v4.f32 [%0], {%1,%2,%3,%4};"
                 :: "l"(gp), "f"(v.x), "f"(v.y), "f"(v.z), "f"(v.w) : "memory");
}
__device__ __forceinline__ ull pack2(float x, float y) {
    ull r; asm("mov.b64 %0, {%1,%2};" : "=l"(r) : "f"(x), "f"(y)); return r;
}
__device__ __forceinline__ ull dup2(float x) {
    ull r; asm("mov.b64 %0, {%1,%1};" : "=l"(r) : "f"(x)); return r;
}
__device__ __forceinline__ void unpack2(ull v, float& x, float& y) {
    asm("mov.b64 {%0,%1}, %2;" : "=f"(x), "=f"(y) : "l"(v));
}
__device__ __forceinline__ void fma2(ull& c, ull a, ull b) {
    asm("fma.rn.f32x2 %0, %1, %2, %0;" : "+l"(c) : "l"(a), "l"(b));
}

// zero helper for per-step buffers: 32768 float4 covering g_rt + g_agg2t
__device__ __forceinline__ void zero_step_chunk(int zi) {
    float4 z = make_float4(0.f, 0.f, 0.f, 0.f);
    if (zi < 16384) ((float4*)g_rt)[zi] = z;
    else            ((float4*)g_agg2t)[zi - 16384] = z;
}

// s-side edge aggregation body (one chunk of work)
__device__ __forceinline__ void agg2s_body(const float* __restrict__ rstep_s,
                                           const int* __restrict__ eis,
                                           float* __restrict__ dst_base, int idx) {
    int e = idx >> 2, q = idx & 3;
    int src = __ldg(eis + e);
    int dst = __ldg(eis + E_ + e);
    float4 v = *(const float4*)(rstep_s + (size_t)src * R_ + q * 4);
    red_add_v4(dst_base + dst * R_ + q * 4, v);
}

// psi2 node + Wm1 fold body: 4 threads/node, 64 nodes per block
__device__ __forceinline__ void node2_body(const float* __restrict__ vsrc,
                                           const float* __restrict__ agsrc,
                                           float* __restrict__ outp_base,
                                           const float* __restrict__ W2s, const float* __restrict__ W2n,
                                           const float* __restrict__ b2, const float* __restrict__ Wm1,
                                           const float* __restrict__ bm1, int use_bm1, int blk) {
    __shared__ float ws[16][17], wn[16][17], wm[16][17], b2s[16], bm1s[16];
    int tid = threadIdx.x;
    {
        int k = tid >> 4, r = tid & 15;
        ws[k][r] = W2s[tid]; wn[k][r] = W2n[tid]; wm[k][r] = Wm1[tid];
    }
    if (tid < 16) { b2s[tid] = b2[tid]; bm1s[tid] = use_bm1 ? bm1[tid] : 0.f; }
    __syncthreads();

    int node = blk * 64 + (tid >> 2);
    int rq = tid & 3;

    float v[16], ag[16];
    #pragma unroll
    for (int q = 0; q < 4; q++) {
        float4 t = *(const float4*)(vsrc + (size_t)node * R_ + q * 4);
        v[q*4] = t.x; v[q*4+1] = t.y; v[q*4+2] = t.z; v[q*4+3] = t.w;
        float4 t2 = *(const float4*)(agsrc + (size_t)node * R_ + q * 4);
        ag[q*4] = t2.x; ag[q*4+1] = t2.y; ag[q*4+2] = t2.z; ag[q*4+3] = t2.w;
    }
    float o[4];
    #pragma unroll
    for (int j = 0; j < 4; j++) {
        int r = rq * 4 + j;
        float acc = b2s[r];
        #pragma unroll
        for (int k = 0; k < 16; k++) acc = fmaf(v[k], ws[k][r], fmaf(ag[k], wn[k][r], acc));
        o[j] = fmaxf(acc, 0.f);
    }
    float res[4];
    #pragma unroll
    for (int j = 0; j < 4; j++) res[j] = bm1s[rq * 4 + j];
    #pragma unroll
    for (int k = 0; k < 16; k++) {
        float ov = __shfl_sync(0xffffffffu, o[k & 3], k >> 2, 4);
        #pragma unroll
        for (int j = 0; j < 4; j++) res[j] = fmaf(ov, wm[k][rq * 4 + j], res[j]);
    }
    float* outp = outp_base + (size_t)node * R_ + rq * 4;
    *(float4*)outp = make_float4(res[0], res[1], res[2], res[3]);
}

// ---------------- psi1 aggregation + tail zero of g_agg2S ----------------
__global__ __launch_bounds__(256) void k_agg1(const float* __restrict__ xs, const int* __restrict__ eis,
                                              const float* __restrict__ xt, const int* __restrict__ eit) {
    int side = blockIdx.y;
    int tid = threadIdx.x;
    if (blockIdx.x >= 8192) {      // 64 tail blocks per side: zero g_agg2S (32768 float4 total)
        int zi = (blockIdx.x - 8192) * 256 + tid + side * 16384;
        ((float4*)g_agg2S)[zi] = make_float4(0.f, 0.f, 0.f, 0.f);
        return;
    }
    const float* x = side ? xt : xs;
    const int* ei  = side ? eit : eis;
    int idx = blockIdx.x * 256 + tid;
    int e = idx >> 5, g = idx & 31;
    int src = __ldg(ei + e);
    int dst = __ldg(ei + E_ + e);
    float4 v = *(const float4*)(x + (size_t)src * F_ + g * 4);
    red_add_v4(&g_agg1[side][dst][g * 4], v);
}

// ---------------- psi1 GEMM + tail agg2s (both steps) ----------------
__global__ __launch_bounds__(256) void k_psi1(const float* __restrict__ xs, const float* __restrict__ xt,
                                              const float* __restrict__ Ws, const float* __restrict__ Wn,
                                              const float* __restrict__ b1,
                                              const float* __restrict__ rsteps, const int* __restrict__ eis) {
    int tid = threadIdx.x;
    if (blockIdx.x >= 64) {        // 1024 tail blocks per y: agg2s for step = blockIdx.y
        int step = blockIdx.y;
        int idx = (blockIdx.x - 64) * 256 + tid;
        agg2s_body(rsteps + (size_t)step * BN_ * R_, eis, &g_agg2S[step][0], idx);
        return;
    }
    __shared__ float As[16][68];
    __shared__ float Bs[16][132];
    int side = blockIdx.y;
    const float* X  = side ? xt : xs;
    const float* AG = &g_agg1[side][0][0];
    int m0 = blockIdx.x * 64;
    int tx = tid & 31, ty = tid >> 5;
    ull acc[4][4];
    #pragma unroll
    for (int i = 0; i < 4; i++)
        #pragma unroll
        for (int j = 0; j < 4; j++) acc[i][j] = 0ull;

    for (int c = 0; c < 16; c++) {
        const float* Asrc = (c < 8) ? X : AG;
        const float* Bsrc = (c < 8) ? Ws : Wn;
        int kb = (c & 7) * 16;
        {
            int r = tid >> 2, kq = tid & 3;
            float4 v = *(const float4*)(Asrc + (size_t)(m0 + r) * F_ + kb + kq * 4);
            As[kq * 4 + 0][r] = v.x; As[kq * 4 + 1][r] = v.y;
            As[kq * 4 + 2][r] = v.z; As[kq * 4 + 3][r] = v.w;
        }
        #pragma unroll
        for (int it = 0; it < 2; it++) {
            int lin = tid + it * 256;
            int kr = lin >> 5, cq = lin & 31;
            float4 v = *(const float4*)(Bsrc + (size_t)(kb + kr) * F_ + cq * 4);
            *(float4*)&Bs[kr][cq * 4] = v;
        }
        __syncthreads();
        #pragma unroll
        for (int k = 0; k < 16; k++) {
            float4 a0 = *(float4*)&As[k][ty * 8];
            float4 a1 = *(float4*)&As[k][ty * 8 + 4];
            ull ap[4] = { pack2(a0.x, a0.y), pack2(a0.z, a0.w),
                          pack2(a1.x, a1.y), pack2(a1.z, a1.w) };
            float4 bv = *(float4*)&Bs[k][tx * 4];
            ull bd[4] = { dup2(bv.x), dup2(bv.y), dup2(bv.z), dup2(bv.w) };
            #pragma unroll
            for (int i = 0; i < 4; i++)
                #pragma unroll
                for (int j = 0; j < 4; j++) fma2(acc[i][j], ap[i], bd[j]);
        }
        __syncthreads();
    }
    float4 bz = *(const float4*)(b1 + tx * 4);
    float bzv[4] = { bz.x, bz.y, bz.z, bz.w };
    #pragma unroll
    for (int i2 = 0; i2 < 4; i2++) {
        float lo[4], hi[4];
        #pragma unroll
        for (int j = 0; j < 4; j++) unpack2(acc[i2][j], lo[j], hi[j]);
        int r0 = m0 + ty * 8 + i2 * 2;
        float4 o0 = make_float4(fmaxf(lo[0] + bzv[0], 0.f), fmaxf(lo[1] + bzv[1], 0.f),
                                fmaxf(lo[2] + bzv[2], 0.f), fmaxf(lo[3] + bzv[3], 0.f));
        float4 o1 = make_float4(fmaxf(hi[0] + bzv[0], 0.f), fmaxf(hi[1] + bzv[1], 0.f),
                                fmaxf(hi[2] + bzv[2], 0.f), fmaxf(hi[3] + bzv[3], 0.f));
        *(float4*)(&g_h[side][r0][tx * 4])     = o0;
        *(float4*)(&g_h[side][r0 + 1][tx * 4]) = o1;
    }
}

// ---------------- S_hat = h_s @ h_t^T ----------------
__global__ __launch_bounds__(256, 2) void k_shat() {
    __shared__ float As[16][132];
    __shared__ float Bs[16][132];
    int b = blockIdx.z, s0 = blockIdx.y * 128, t0 = blockIdx.x * 128;
    const float* Hs = &g_h[0][b * N_][0];
    const float* Ht = &g_h[1][b * N_][0];
    int tid = threadIdx.x;
    int tx = tid & 15, ty = tid >> 4;
    ull acc[4][8];
    #pragma unroll
    for (int i = 0; i < 4; i++)
        #pragma unroll
        for (int j = 0; j < 8; j++) acc[i][j] = 0ull;

    for (int c = 0; c < 8; c++) {
        int kb = c * 16;
        #pragma unroll
        for (int it = 0; it < 2; it++) {
            int lin = tid + it * 256;
            int r = lin >> 2, kq = lin & 3;
            float4 va = *(const float4*)(Hs + (size_t)(s0 + r) * F_ + kb + kq * 4);
            As[kq * 4 + 0][r] = va.x; As[kq * 4 + 1][r] = va.y;
            As[kq * 4 + 2][r] = va.z; As[kq * 4 + 3][r] = va.w;
            float4 vb = *(const float4*)(Ht + (size_t)(t0 + r) * F_ + kb + kq * 4);
            Bs[kq * 4 + 0][r] = vb.x; Bs[kq * 4 + 1][r] = vb.y;
            Bs[kq * 4 + 2][r] = vb.z; Bs[kq * 4 + 3][r] = vb.w;
        }
        __syncthreads();
        #pragma unroll
        for (int k = 0; k < 16; k++) {
            float4 a0 = *(float4*)&As[k][ty * 8];
            float4 a1 = *(float4*)&As[k][ty * 8 + 4];
            ull ap[4] = { pack2(a0.x, a0.y), pack2(a0.z, a0.w),
                          pack2(a1.x, a1.y), pack2(a1.z, a1.w) };
            float4 bA = *(float4*)&Bs[k][tx * 4];
            float4 bB = *(float4*)&Bs[k][64 + tx * 4];
            ull bd[8] = { dup2(bA.x), dup2(bA.y), dup2(bA.z), dup2(bA.w),
                          dup2(bB.x), dup2(bB.y), dup2(bB.z), dup2(bB.w) };
            #pragma unroll
            for (int i = 0; i < 4; i++)
                #pragma unroll
                for (int j = 0; j < 8; j++) fma2(acc[i][j], ap[i], bd[j]);
        }
        __syncthreads();
    }
    #pragma unroll
    for (int i2 = 0; i2 < 4; i2++) {
        float lo[8], hi[8];
        #pragma unroll
        for (int j = 0; j < 8; j++) unpack2(acc[i2][j], lo[j], hi[j]);
        int r0 = s0 + ty * 8 + i2 * 2;
        float* base0 = g_Shat + (size_t)(b * N_ + r0) * N_;
        float* base1 = base0 + N_;
        *(float4*)(base0 + t0 + tx * 4)      = make_float4(lo[0], lo[1], lo[2], lo[3]);
        *(float4*)(base0 + t0 + 64 + tx * 4) = make_float4(lo[4], lo[5], lo[6], lo[7]);
        *(float4*)(base1 + t0 + tx * 4)      = make_float4(hi[0], hi[1], hi[2], hi[3]);
        *(float4*)(base1 + t0 + 64 + tx * 4) = make_float4(hi[4], hi[5], hi[6], hi[7]);
    }
}

// ---------------- softmax + tails: node2s (both steps) + zero step buffers ----------------
__global__ __launch_bounds__(256) void k_softmax_row(float* __restrict__ out,
                                                     const float* __restrict__ rsteps,
                                                     const float* __restrict__ W2s, const float* __restrict__ W2n,
                                                     const float* __restrict__ b2, const float* __restrict__ Wm1,
                                                     const float* __restrict__ bm1) {
    int tid = threadIdx.x;
    if (blockIdx.x >= 1152) {                 // 128 blocks: zero g_rt + g_agg2t for step 0
        zero_step_chunk((blockIdx.x - 1152) * 256 + tid);
        return;
    }
    if (blockIdx.x >= 1024) {                 // 128 blocks: node2s, 64 per step
        int nb = blockIdx.x - 1024;
        int step = nb >> 6;
        node2_body(rsteps + (size_t)step * BN_ * R_, &g_agg2S[step][0], &g_a2[step][0],
                   W2s, W2n, b2, Wm1, bm1, 1, nb & 63);
        return;
    }
    __shared__ float red_m[4][2], red_s[4][2];
    int rl = tid >> 6, lane = tid & 63;
    int row = blockIdx.x * 4 + rl;
    const float* srow = g_Shat + (size_t)row * N_;
    float4 v[4];
    #pragma unroll
    for (int q = 0; q < 4; q++) v[q] = *(const float4*)(srow + q * 256 + lane * 4);
    float lm = -3.4e38f;
    #pragma unroll
    for (int q = 0; q < 4; q++)
        lm = fmaxf(lm, fmaxf(fmaxf(v[q].x, v[q].y), fmaxf(v[q].z, v[q].w)));
    #pragma unroll
    for (int o = 16; o; o >>= 1) lm = fmaxf(lm, __shfl_xor_sync(0xffffffffu, lm, o));
    if ((tid & 31) == 0) red_m[rl][(tid >> 5) & 1] = lm;
    __syncthreads();
    float M = fmaxf(red_m[rl][0], red_m[rl][1]);
    float s = 0.f;
    #pragma unroll
    for (int q = 0; q < 4; q++) {
        v[q].x = __expf(v[q].x - M); v[q].y = __expf(v[q].y - M);
        v[q].z = __expf(v[q].z - M); v[q].w = __expf(v[q].w - M);
        s += (v[q].x + v[q].y) + (v[q].z + v[q].w);
    }
    #pragma unroll
    for (int o = 16; o; o >>= 1) s += __shfl_xor_sync(0xffffffffu, s, o);
    if ((tid & 31) == 0) red_s[rl][(tid >> 5) & 1] = s;
    __syncthreads();
    float inv = 1.f / (red_s[rl][0] + red_s[rl][1]);
    float* orow = out + (size_t)row * N_;
    #pragma unroll
    for (int q = 0; q < 4; q++)
        *(float4*)(orow + q * 256 + lane * 4) =
            make_float4(v[q].x * inv, v[q].y * inv, v[q].z * inv, v[q].w * inv);
    if (lane == 0) { g_rowmax[row] = M; g_rowinv[row] = inv; }
}

// ---------------- r_t = S^T @ r_s, split-s with atomic combine ----------------
__global__ __launch_bounds__(256) void k_rt(const float* __restrict__ rstep) {
    __shared__ float w[16][132];
    __shared__ float rsv[16][16];
    int b = blockIdx.z, t0 = blockIdx.x * 128, sbase = blockIdx.y * 128;
    int tid = threadIdx.x;
    int tl = tid & 127;
    int rh = (tid >> 7) * 8;
    float acc[8] = {0.f,0.f,0.f,0.f,0.f,0.f,0.f,0.f};
    for (int sc = 0; sc < 8; sc++) {
        int s0 = sbase + sc * 16;
        {
            int si = tid >> 4, cq = (tid & 15) * 8;
            int row = b * N_ + s0 + si;
            float M = g_rowmax[row], inv = g_rowinv[row];
            const float* sp = g_Shat + (size_t)row * N_ + t0 + cq;
            float4 v0 = *(const float4*)sp;
            float4 v1 = *(const float4*)(sp + 4);
            w[si][cq + 0] = __expf(v0.x - M) * inv;
            w[si][cq + 1] = __expf(v0.y - M) * inv;
            w[si][cq + 2] = __expf(v0.z - M) * inv;
            w[si][cq + 3] = __expf(v0.w - M) * inv;
            w[si][cq + 4] = __expf(v1.x - M) * inv;
            w[si][cq + 5] = __expf(v1.y - M) * inv;
            w[si][cq + 6] = __expf(v1.z - M) * inv;
            w[si][cq + 7] = __expf(v1.w - M) * inv;
        }
        if (tid < 64) {
            int si = tid >> 2, rq = (tid & 3) * 4;
            *(float4*)&rsv[si][rq] = *(const float4*)(rstep + (size_t)(b * N_ + s0 + si) * R_ + rq);
        }
        __syncthreads();
        #pragma unroll
        for (int si = 0; si < 16; si++) {
            float wv = w[si][tl];
            #pragma unroll
            for (int r = 0; r < 8; r++) acc[r] = fmaf(wv, rsv[si][rh + r], acc[r]);
        }
        __syncthreads();
    }
    float* dst = g_rt + (size_t)(b * N_ + t0 + tl) * R_ + rh;
    red_add_v4(dst,     make_float4(acc[0], acc[1], acc[2], acc[3]));
    red_add_v4(dst + 4, make_float4(acc[4], acc[5], acc[6], acc[7]));
}

// ---------------- psi2 t-side edge aggregation ----------------
__global__ __launch_bounds__(256) void k_agg2t(const int* __restrict__ eit) {
    int idx = blockIdx.x * 256 + threadIdx.x;
    int e = idx >> 2, q = idx & 3;
    int src = __ldg(eit + e);
    int dst = __ldg(eit + E_ + e);
    float4 v = *(const float4*)(g_rt + (size_t)src * R_ + q * 4);
    red_add_v4(&g_agg2t[dst * R_ + q * 4], v);
}

// ---------------- psi2 t-side node ----------------
__global__ __launch_bounds__(256) void k_node2t(const float* __restrict__ W2s, const float* __restrict__ W2n,
                                                const float* __restrict__ b2, const float* __restrict__ Wm1,
                                                const float* __restrict__ bm1) {
    node2_body(g_rt, g_agg2t, g_c, W2s, W2n, b2, Wm1, bm1, 0, blockIdx.x);
}

// ---------------- fused update + softmax: 8 rows/block, batched reductions ----------------
__global__ __launch_bounds__(256) void k_update(const float* __restrict__ Wm2, const float* __restrict__ bm2,
                                                const float* __restrict__ a_step,
                                                int last, float* __restrict__ outL) {
    int tid = threadIdx.x;
    if (blockIdx.x >= 512) {                  // 128 tail blocks: zero step buffers for step 1
        if (!last) zero_step_chunk((blockIdx.x - 512) * 256 + tid);
        return;
    }
    __shared__ float a_sh[8][17];
    __shared__ float wm2s[16];
    __shared__ float redm[8][8], reds[8][8];
    __shared__ float bshared;
    int b = blockIdx.x >> 7;
    int rbase = b * N_ + (blockIdx.x & 127) * 8;
    int wid = tid >> 5, lane = tid & 31;

    float c_r[64];
    const float* cp = g_c + (size_t)(b * N_ + tid * 4) * R_;
    #pragma unroll
    for (int j = 0; j < 4; j++)
        #pragma unroll
        for (int q = 0; q < 4; q++)
            *(float4*)&c_r[j * 16 + q * 4] = *(const float4*)(cp + j * R_ + q * 4);

    if (tid < 16) wm2s[tid] = Wm2[tid];
    if (tid == 0) bshared = bm2[0];
    if (tid < 128) {
        int i = tid >> 4, k = tid & 15;
        a_sh[i][k] = a_step[(size_t)(rbase + i) * R_ + k];
    }
    __syncthreads();

    float4 sh[8];
    #pragma unroll
    for (int i = 0; i < 8; i++)
        sh[i] = *(const float4*)(g_Shat + (size_t)(rbase + i) * N_ + tid * 4);

    float nv[8][4];
    #pragma unroll
    for (int i = 0; i < 8; i++) {
        #pragma unroll
        for (int j = 0; j < 4; j++) {
            float upd = bshared;
            #pragma unroll
            for (int k = 0; k < 16; k++)
                upd = fmaf(fmaxf(a_sh[i][k] - c_r[j * 16 + k], 0.f), wm2s[k], upd);
            nv[i][j] = ((const float*)&sh[i])[j] + upd;
        }
    }

    float lm[8];
    #pragma unroll
    for (int i = 0; i < 8; i++)
        lm[i] = fmaxf(fmaxf(nv[i][0], nv[i][1]), fmaxf(nv[i][2], nv[i][3]));
    #pragma unroll
    for (int o = 16; o; o >>= 1)
        #pragma unroll
        for (int i = 0; i < 8; i++)
            lm[i] = fmaxf(lm[i], __shfl_xor_sync(0xffffffffu, lm[i], o));
    if (lane == 0)
        #pragma unroll
        for (int i = 0; i < 8; i++) redm[i][wid] = lm[i];
    __syncthreads();
    float M[8];
    #pragma unroll
    for (int i = 0; i < 8; i++) {
        float m = redm[i][0];
        #pragma unroll
        for (int wq = 1; wq < 8; wq++) m = fmaxf(m, redm[i][wq]);
        M[i] = m;
    }

    float s[8];
    #pragma unroll
    for (int i = 0; i < 8; i++) {
        float e0 = __expf(nv[i][0] - M[i]), e1 = __expf(nv[i][1] - M[i]);
        float e2 = __expf(nv[i][2] - M[i]), e3 = __expf(nv[i][3] - M[i]);
        s[i] = (e0 + e1) + (e2 + e3);
        if (last) { nv[i][0] = e0; nv[i][1] = e1; nv[i][2] = e2; nv[i][3] = e3; }
    }
    #pragma unroll
    for (int o = 16; o; o >>= 1)
        #pragma unroll
        for (int i = 0; i < 8; i++)
            s[i] += __shfl_xor_sync(0xffffffffu, s[i], o);
    if (lane == 0)
        #pragma unroll
        for (int i = 0; i < 8; i++) reds[i][wid] = s[i];
    __syncthreads();

    #pragma unroll
    for (int i = 0; i < 8; i++) {
        float S = reds[i][0];
        #pragma unroll
        for (int wq = 1; wq < 8; wq++) S += reds[i][wq];
        float inv = 1.f / S;
        int row = rbase + i;
        if (last) {
            *(float4*)(outL + (size_t)row * N_ + tid * 4) =
                make_float4(nv[i][0] * inv, nv[i][1] * inv, nv[i][2] * inv, nv[i][3] * inv);
        } else {
            *(float4*)(g_Shat + (size_t)row * N_ + tid * 4) =
                make_float4(nv[i][0], nv[i][1], nv[i][2], nv[i][3]);
            if (tid == 0) { g_rowmax[row] = M[i]; g_rowinv[row] = inv; }
        }
    }
}

// ---------------- launcher ----------------
extern "C" void kernel_launch(void* const* d_in, const int* in_sizes, int n_in,
                              void* d_out, int out_size) {
    const float* x_s = (const float*)d_in[0];
    const int*   eis = (const int*)d_in[1];
    const float* x_t = (const float*)d_in[2];
    const int*   eit = (const int*)d_in[3];
    const float* W1s = (const float*)d_in[4];
    const float* W1n = (const float*)d_in[5];
    const float* b1  = (const float*)d_in[6];
    const float* W2s = (const float*)d_in[7];
    const float* W2n = (const float*)d_in[8];
    const float* b2  = (const float*)d_in[9];
    const float* Wm1 = (const float*)d_in[10];
    const float* bm1 = (const float*)d_in[11];
    const float* Wm2 = (const float*)d_in[12];
    const float* bm2 = (const float*)d_in[13];
    const float* rsteps = (const float*)d_in[14];
    float* out = (float*)d_out;

    void *p_agg1 = nullptr, *p_a2 = nullptr;
    cudaGetSymbolAddress(&p_agg1, g_agg1);
    cudaGetSymbolAddress(&p_a2, g_a2);
    const float* a_base = (const float*)p_a2;
    float* outL = out + (size_t)B_ * N_ * N_;

    cudaMemsetAsync(p_agg1, 0, sizeof(float) * 2 * BN_ * F_);
    k_agg1<<<dim3(8192 + 64, 2), 256>>>(x_s, eis, x_t, eit);
    k_psi1<<<dim3(64 + 1024, 2), 256>>>(x_s, x_t, W1s, W1n, b1, rsteps, eis);
    k_shat<<<dim3(8, 8, 4), 256>>>();
    k_softmax_row<<<1024 + 128 + 128, 256>>>(out, rsteps, W2s, W2n, b2, Wm1, bm1);

    for (int i = 0; i < 2; i++) {
        k_rt<<<dim3(8, 8, 4), 256>>>(rsteps + (size_t)i * BN_ * R_);
        k_agg2t<<<E_ * 4 / 256, 256>>>(eit);
        k_node2t<<<BN_ / 64, 256>>>(W2s, W2n, b2, Wm1, bm1);
        int grid_u = (i == 0) ? (512 + 128) : 512;
        k_update<<<grid_u, 256>>>(Wm2, bm2, a_base + (size_t)i * BN_ * R_,
                                  (i == 1) ? 1 : 0, outL);
    }
}

// round 15
// speedup vs baseline: 1.7799x; 1.7799x over previous
#include <cuda_runtime.h>

typedef unsigned long long ull;

#define B_  4
#define N_  1024
#define F_  128
#define R_  16
#define E_  65536
#define BN_ 4096

// ---------------- device scratch ----------------
__device__ __align__(16) float g_agg1[2][BN_][F_];
__device__ __align__(16) float g_h[2][BN_][F_];
__device__ __align__(16) float g_Shat[(size_t)B_ * N_ * N_];
__device__ float g_rowmax[BN_];
__device__ float g_rowinv[BN_];
__device__ __align__(16) float g_rt[BN_ * R_];
__device__ __align__(16) float g_agg2[2][BN_ * R_];
__device__ __align__(16) float g_a[BN_ * R_];
__device__ __align__(16) float g_c[BN_ * R_];

// ---------------- helpers ----------------
__device__ __forceinline__ void red_add_v4(float* p, float4 v) {
    ull gp = (ull)__cvta_generic_to_global(p);
    asm volatile("red.global.add.v4.f32 [%0], {%1,%2,%3,%4};"
                 :: "l"(gp), "f"(v.x), "f"(v.y), "f"(v.z), "f"(v.w) : "memory");
}
__device__ __forceinline__ ull pack2(float x, float y) {
    ull r; asm("mov.b64 %0, {%1,%2};" : "=l"(r) : "f"(x), "f"(y)); return r;
}
__device__ __forceinline__ ull dup2(float x) {
    ull r; asm("mov.b64 %0, {%1,%1};" : "=l"(r) : "f"(x)); return r;
}
__device__ __forceinline__ void unpack2(ull v, float& x, float& y) {
    asm("mov.b64 {%0,%1}, %2;" : "=f"(x), "=f"(y) : "l"(v));
}
__device__ __forceinline__ void fma2(ull& c, ull a, ull b) {
    asm("fma.rn.f32x2 %0, %1, %2, %0;" : "+l"(c) : "l"(a), "l"(b));
}

// zero helper: 49152 float4 covering g_rt + g_agg2
__device__ __forceinline__ void zero_step_chunk(int zi) {
    float4 z = make_float4(0.f, 0.f, 0.f, 0.f);
    if (zi < 16384) ((float4*)g_rt)[zi] = z;
    else            ((float4*)g_agg2)[zi - 16384] = z;
}

// ---------------- psi1 aggregation ----------------
__global__ __launch_bounds__(256) void k_agg1(const float* __restrict__ xs, const int* __restrict__ eis,
                                              const float* __restrict__ xt, const int* __restrict__ eit) {
    int side = blockIdx.y;
    const float* x = side ? xt : xs;
    const int* ei  = side ? eit : eis;
    int idx = blockIdx.x * 256 + threadIdx.x;
    int e = idx >> 5, g = idx & 31;
    int src = __ldg(ei + e);
    int dst = __ldg(ei + E_ + e);
    float4 v = *(const float4*)(x + (size_t)src * F_ + g * 4);
    red_add_v4(&g_agg1[side][dst][g * 4], v);
}

// ---------------- psi1: h = relu(x@W1s + agg@W1n + b1) ----------------
__global__ __launch_bounds__(256) void k_psi1(const float* __restrict__ xs, const float* __restrict__ xt,
                                              const float* __restrict__ Ws, const float* __restrict__ Wn,
                                              const float* __restrict__ b1) {
    __shared__ float As[16][68];
    __shared__ float Bs[16][132];
    int side = blockIdx.y;
    const float* X  = side ? xt : xs;
    const float* AG = &g_agg1[side][0][0];
    int m0 = blockIdx.x * 64;
    int tid = threadIdx.x;
    int tx = tid & 31, ty = tid >> 5;
    ull acc[4][4];
    #pragma unroll
    for (int i = 0; i < 4; i++)
        #pragma unroll
        for (int j = 0; j < 4; j++) acc[i][j] = 0ull;

    for (int c = 0; c < 16; c++) {
        const float* Asrc = (c < 8) ? X : AG;
        const float* Bsrc = (c < 8) ? Ws : Wn;
        int kb = (c & 7) * 16;
        {
            int r = tid >> 2, kq = tid & 3;
            float4 v = *(const float4*)(Asrc + (size_t)(m0 + r) * F_ + kb + kq * 4);
            As[kq * 4 + 0][r] = v.x; As[kq * 4 + 1][r] = v.y;
            As[kq * 4 + 2][r] = v.z; As[kq * 4 + 3][r] = v.w;
        }
        #pragma unroll
        for (int it = 0; it < 2; it++) {
            int lin = tid + it * 256;
            int kr = lin >> 5, cq = lin & 31;
            float4 v = *(const float4*)(Bsrc + (size_t)(kb + kr) * F_ + cq * 4);
            *(float4*)&Bs[kr][cq * 4] = v;
        }
        __syncthreads();
        #pragma unroll
        for (int k = 0; k < 16; k++) {
            float4 a0 = *(float4*)&As[k][ty * 8];
            float4 a1 = *(float4*)&As[k][ty * 8 + 4];
            ull ap[4] = { pack2(a0.x, a0.y), pack2(a0.z, a0.w),
                          pack2(a1.x, a1.y), pack2(a1.z, a1.w) };
            float4 bv = *(float4*)&Bs[k][tx * 4];
            ull bd[4] = { dup2(bv.x), dup2(bv.y), dup2(bv.z), dup2(bv.w) };
            #pragma unroll
            for (int i = 0; i < 4; i++)
                #pragma unroll
                for (int j = 0; j < 4; j++) fma2(acc[i][j], ap[i], bd[j]);
        }
        __syncthreads();
    }
    float4 bz = *(const float4*)(b1 + tx * 4);
    float bzv[4] = { bz.x, bz.y, bz.z, bz.w };
    #pragma unroll
    for (int i2 = 0; i2 < 4; i2++) {
        float lo[4], hi[4];
        #pragma unroll
        for (int j = 0; j < 4; j++) unpack2(acc[i2][j], lo[j], hi[j]);
        int r0 = m0 + ty * 8 + i2 * 2;
        float4 o0 = make_float4(fmaxf(lo[0] + bzv[0], 0.f), fmaxf(lo[1] + bzv[1], 0.f),
                                fmaxf(lo[2] + bzv[2], 0.f), fmaxf(lo[3] + bzv[3], 0.f));
        float4 o1 = make_float4(fmaxf(hi[0] + bzv[0], 0.f), fmaxf(hi[1] + bzv[1], 0.f),
                                fmaxf(hi[2] + bzv[2], 0.f), fmaxf(hi[3] + bzv[3], 0.f));
        *(float4*)(&g_h[side][r0][tx * 4])     = o0;
        *(float4*)(&g_h[side][r0 + 1][tx * 4]) = o1;
    }
}

// ---------------- S_hat = h_s @ h_t^T ----------------
__global__ __launch_bounds__(256, 2) void k_shat() {
    __shared__ float As[16][132];
    __shared__ float Bs[16][132];
    int b = blockIdx.z, s0 = blockIdx.y * 128, t0 = blockIdx.x * 128;
    const float* Hs = &g_h[0][b * N_][0];
    const float* Ht = &g_h[1][b * N_][0];
    int tid = threadIdx.x;
    int tx = tid & 15, ty = tid >> 4;
    ull acc[4][8];
    #pragma unroll
    for (int i = 0; i < 4; i++)
        #pragma unroll
        for (int j = 0; j < 8; j++) acc[i][j] = 0ull;

    for (int c = 0; c < 8; c++) {
        int kb = c * 16;
        #pragma unroll
        for (int it = 0; it < 2; it++) {
            int lin = tid + it * 256;
            int r = lin >> 2, kq = lin & 3;
            float4 va = *(const float4*)(Hs + (size_t)(s0 + r) * F_ + kb + kq * 4);
            As[kq * 4 + 0][r] = va.x; As[kq * 4 + 1][r] = va.y;
            As[kq * 4 + 2][r] = va.z; As[kq * 4 + 3][r] = va.w;
            float4 vb = *(const float4*)(Ht + (size_t)(t0 + r) * F_ + kb + kq * 4);
            Bs[kq * 4 + 0][r] = vb.x; Bs[kq * 4 + 1][r] = vb.y;
            Bs[kq * 4 + 2][r] = vb.z; Bs[kq * 4 + 3][r] = vb.w;
        }
        __syncthreads();
        #pragma unroll
        for (int k = 0; k < 16; k++) {
            float4 a0 = *(float4*)&As[k][ty * 8];
            float4 a1 = *(float4*)&As[k][ty * 8 + 4];
            ull ap[4] = { pack2(a0.x, a0.y), pack2(a0.z, a0.w),
                          pack2(a1.x, a1.y), pack2(a1.z, a1.w) };
            float4 bA = *(float4*)&Bs[k][tx * 4];
            float4 bB = *(float4*)&Bs[k][64 + tx * 4];
            ull bd[8] = { dup2(bA.x), dup2(bA.y), dup2(bA.z), dup2(bA.w),
                          dup2(bB.x), dup2(bB.y), dup2(bB.z), dup2(bB.w) };
            #pragma unroll
            for (int i = 0; i < 4; i++)
                #pragma unroll
                for (int j = 0; j < 8; j++) fma2(acc[i][j], ap[i], bd[j]);
        }
        __syncthreads();
    }
    #pragma unroll
    for (int i2 = 0; i2 < 4; i2++) {
        float lo[8], hi[8];
        #pragma unroll
        for (int j = 0; j < 8; j++) unpack2(acc[i2][j], lo[j], hi[j]);
        int r0 = s0 + ty * 8 + i2 * 2;
        float* base0 = g_Shat + (size_t)(b * N_ + r0) * N_;
        float* base1 = base0 + N_;
        *(float4*)(base0 + t0 + tx * 4)      = make_float4(lo[0], lo[1], lo[2], lo[3]);
        *(float4*)(base0 + t0 + 64 + tx * 4) = make_float4(lo[4], lo[5], lo[6], lo[7]);
        *(float4*)(base1 + t0 + tx * 4)      = make_float4(hi[0], hi[1], hi[2], hi[3]);
        *(float4*)(base1 + t0 + 64 + tx * 4) = make_float4(hi[4], hi[5], hi[6], hi[7]);
    }
}

// ---------------- initial softmax: 4 rows/block, 2 warps/row; tail blocks zero step buffers ----------------
__global__ __launch_bounds__(256) void k_softmax_row(float* __restrict__ out) {
    int tid = threadIdx.x;
    if (blockIdx.x >= 1024) {                 // 192 tail blocks: zero g_rt + g_agg2 for step 0
        zero_step_chunk((blockIdx.x - 1024) * 256 + tid);
        return;
    }
    __shared__ float red_m[4][2], red_s[4][2];
    int rl = tid >> 6, lane = tid & 63;
    int row = blockIdx.x * 4 + rl;
    const float* srow = g_Shat + (size_t)row * N_;
    float4 v[4];
    #pragma unroll
    for (int q = 0; q < 4; q++) v[q] = *(const float4*)(srow + q * 256 + lane * 4);
    float lm = -3.4e38f;
    #pragma unroll
    for (int q = 0; q < 4; q++)
        lm = fmaxf(lm, fmaxf(fmaxf(v[q].x, v[q].y), fmaxf(v[q].z, v[q].w)));
    #pragma unroll
    for (int o = 16; o; o >>= 1) lm = fmaxf(lm, __shfl_xor_sync(0xffffffffu, lm, o));
    if ((tid & 31) == 0) red_m[rl][(tid >> 5) & 1] = lm;
    __syncthreads();
    float M = fmaxf(red_m[rl][0], red_m[rl][1]);
    float s = 0.f;
    #pragma unroll
    for (int q = 0; q < 4; q++) {
        v[q].x = __expf(v[q].x - M); v[q].y = __expf(v[q].y - M);
        v[q].z = __expf(v[q].z - M); v[q].w = __expf(v[q].w - M);
        s += (v[q].x + v[q].y) + (v[q].z + v[q].w);
    }
    #pragma unroll
    for (int o = 16; o; o >>= 1) s += __shfl_xor_sync(0xffffffffu, s, o);
    if ((tid & 31) == 0) red_s[rl][(tid >> 5) & 1] = s;
    __syncthreads();
    float inv = 1.f / (red_s[rl][0] + red_s[rl][1]);
    float* orow = out + (size_t)row * N_;
    #pragma unroll
    for (int q = 0; q < 4; q++)
        *(float4*)(orow + q * 256 + lane * 4) =
            make_float4(v[q].x * inv, v[q].y * inv, v[q].z * inv, v[q].w * inv);
    if (lane == 0) { g_rowmax[row] = M; g_rowinv[row] = inv; }
}

// ---------------- r_t = S^T @ r_s, split-s with atomic combine ----------------
__global__ __launch_bounds__(256) void k_rt(const float* __restrict__ rstep) {
    __shared__ float w[16][132];
    __shared__ float rsv[16][16];
    int b = blockIdx.z, t0 = blockIdx.x * 128, sbase = blockIdx.y * 128;
    int tid = threadIdx.x;
    int tl = tid & 127;
    int rh = (tid >> 7) * 8;
    float acc[8] = {0.f,0.f,0.f,0.f,0.f,0.f,0.f,0.f};
    for (int sc = 0; sc < 8; sc++) {
        int s0 = sbase + sc * 16;
        {
            int si = tid >> 4, cq = (tid & 15) * 8;
            int row = b * N_ + s0 + si;
            float M = g_rowmax[row], inv = g_rowinv[row];
            const float* sp = g_Shat + (size_t)row * N_ + t0 + cq;
            float4 v0 = *(const float4*)sp;
            float4 v1 = *(const float4*)(sp + 4);
            w[si][cq + 0] = __expf(v0.x - M) * inv;
            w[si][cq + 1] = __expf(v0.y - M) * inv;
            w[si][cq + 2] = __expf(v0.z - M) * inv;
            w[si][cq + 3] = __expf(v0.w - M) * inv;
            w[si][cq + 4] = __expf(v1.x - M) * inv;
            w[si][cq + 5] = __expf(v1.y - M) * inv;
            w[si][cq + 6] = __expf(v1.z - M) * inv;
            w[si][cq + 7] = __expf(v1.w - M) * inv;
        }
        if (tid < 64) {
            int si = tid >> 2, rq = (tid & 3) * 4;
            *(float4*)&rsv[si][rq] = *(const float4*)(rstep + (size_t)(b * N_ + s0 + si) * R_ + rq);
        }
        __syncthreads();
        #pragma unroll
        for (int si = 0; si < 16; si++) {
            float wv = w[si][tl];
            #pragma unroll
            for (int r = 0; r < 8; r++) acc[r] = fmaf(wv, rsv[si][rh + r], acc[r]);
        }
        __syncthreads();
    }
    float* dst = g_rt + (size_t)(b * N_ + t0 + tl) * R_ + rh;
    red_add_v4(dst,     make_float4(acc[0], acc[1], acc[2], acc[3]));
    red_add_v4(dst + 4, make_float4(acc[4], acc[5], acc[6], acc[7]));
}

// ---------------- psi2 edge aggregation ----------------
__global__ __launch_bounds__(256) void k_agg2(const float* __restrict__ rstep,
                                              const int* __restrict__ eis, const int* __restrict__ eit) {
    int side = blockIdx.y;
    const float* x = side ? g_rt : rstep;
    const int* ei  = side ? eit : eis;
    int idx = blockIdx.x * 256 + threadIdx.x;
    int e = idx >> 2, q = idx & 3;
    int src = __ldg(ei + e);
    int dst = __ldg(ei + E_ + e);
    float4 v = *(const float4*)(x + (size_t)src * R_ + q * 4);
    red_add_v4(&g_agg2[side][dst * R_ + q * 4], v);
}

// ---------------- psi2 node + Wm1 fold: 4 threads/node ----------------
__global__ __launch_bounds__(256) void k_node2(const float* __restrict__ rstep,
                                               const float* __restrict__ W2s, const float* __restrict__ W2n,
                                               const float* __restrict__ b2, const float* __restrict__ Wm1,
                                               const float* __restrict__ bm1) {
    __shared__ float ws[16][17], wn[16][17], wm[16][17], b2s[16], bm1s[16];
    int side = blockIdx.y;
    int tid = threadIdx.x;
    {
        int k = tid >> 4, r = tid & 15;
        ws[k][r] = W2s[tid]; wn[k][r] = W2n[tid]; wm[k][r] = Wm1[tid];
    }
    if (tid < 16) { b2s[tid] = b2[tid]; bm1s[tid] = (side == 0) ? bm1[tid] : 0.f; }
    __syncthreads();

    int node = blockIdx.x * 64 + (tid >> 2);
    int rq = tid & 3;
    const float* vsrc = side ? g_rt : rstep;

    float v[16], ag[16];
    #pragma unroll
    for (int q = 0; q < 4; q++) {
        float4 t = *(const float4*)(vsrc + (size_t)node * R_ + q * 4);
        v[q*4] = t.x; v[q*4+1] = t.y; v[q*4+2] = t.z; v[q*4+3] = t.w;
        float4 t2 = *(const float4*)(&g_agg2[side][node * R_ + q * 4]);
        ag[q*4] = t2.x; ag[q*4+1] = t2.y; ag[q*4+2] = t2.z; ag[q*4+3] = t2.w;
    }
    float o[4];
    #pragma unroll
    for (int j = 0; j < 4; j++) {
        int r = rq * 4 + j;
        float acc = b2s[r];
        #pragma unroll
        for (int k = 0; k < 16; k++) acc = fmaf(v[k], ws[k][r], fmaf(ag[k], wn[k][r], acc));
        o[j] = fmaxf(acc, 0.f);
    }
    float res[4];
    #pragma unroll
    for (int j = 0; j < 4; j++) res[j] = bm1s[rq * 4 + j];
    #pragma unroll
    for (int k = 0; k < 16; k++) {
        float ov = __shfl_sync(0xffffffffu, o[k & 3], k >> 2, 4);
        #pragma unroll
        for (int j = 0; j < 4; j++) res[j] = fmaf(ov, wm[k][rq * 4 + j], res[j]);
    }
    float* outp = (side ? g_c : g_a) + (size_t)node * R_ + rq * 4;
    *(float4*)outp = make_float4(res[0], res[1], res[2], res[3]);
}

// ---------------- fused update + softmax: 8 rows/block, BATCHED reductions ----------------
__global__ __launch_bounds__(256) void k_update(const float* __restrict__ Wm2, const float* __restrict__ bm2,
                                                int last, float* __restrict__ outL) {
    int tid = threadIdx.x;
    if (blockIdx.x >= 512) {                  // 192 tail blocks: zero step buffers for step 1
        if (!last) zero_step_chunk((blockIdx.x - 512) * 256 + tid);
        return;
    }
    __shared__ float a_sh[8][17];
    __shared__ float wm2s[16];
    __shared__ float redm[8][8], reds[8][8];  // [row][warp]
    __shared__ float bshared;
    int b = blockIdx.x >> 7;
    int rbase = b * N_ + (blockIdx.x & 127) * 8;
    int wid = tid >> 5, lane = tid & 31;

    float c_r[64];
    const float* cp = g_c + (size_t)(b * N_ + tid * 4) * R_;
    #pragma unroll
    for (int j = 0; j < 4; j++)
        #pragma unroll
        for (int q = 0; q < 4; q++)
            *(float4*)&c_r[j * 16 + q * 4] = *(const float4*)(cp + j * R_ + q * 4);

    if (tid < 16) wm2s[tid] = Wm2[tid];
    if (tid == 0) bshared = bm2[0];
    if (tid < 128) {
        int i = tid >> 4, k = tid & 15;
        a_sh[i][k] = g_a[(size_t)(rbase + i) * R_ + k];
    }
    __syncthreads();

    // phase 1: all 8 rows' new scores into registers
    float4 sh[8];
    #pragma unroll
    for (int i = 0; i < 8; i++)
        sh[i] = *(const float4*)(g_Shat + (size_t)(rbase + i) * N_ + tid * 4);

    float nv[8][4];
    #pragma unroll
    for (int i = 0; i < 8; i++) {
        #pragma unroll
        for (int j = 0; j < 4; j++) {
            float upd = bshared;
            #pragma unroll
            for (int k = 0; k < 16; k++)
                upd = fmaf(fmaxf(a_sh[i][k] - c_r[j * 16 + k], 0.f), wm2s[k], upd);
            nv[i][j] = ((const float*)&sh[i])[j] + upd;
        }
    }

    // phase 2: batched max reduction
    float lm[8];
    #pragma unroll
    for (int i = 0; i < 8; i++)
        lm[i] = fmaxf(fmaxf(nv[i][0], nv[i][1]), fmaxf(nv[i][2], nv[i][3]));
    #pragma unroll
    for (int o = 16; o; o >>= 1)
        #pragma unroll
        for (int i = 0; i < 8; i++)
            lm[i] = fmaxf(lm[i], __shfl_xor_sync(0xffffffffu, lm[i], o));
    if (lane == 0)
        #pragma unroll
        for (int i = 0; i < 8; i++) redm[i][wid] = lm[i];
    __syncthreads();
    float M[8];
    #pragma unroll
    for (int i = 0; i < 8; i++) {
        float m = redm[i][0];
        #pragma unroll
        for (int wq = 1; wq < 8; wq++) m = fmaxf(m, redm[i][wq]);
        M[i] = m;
    }

    // phase 3: batched exp-sum reduction
    float s[8];
    #pragma unroll
    for (int i = 0; i < 8; i++) {
        float e0 = __expf(nv[i][0] - M[i]), e1 = __expf(nv[i][1] - M[i]);
        float e2 = __expf(nv[i][2] - M[i]), e3 = __expf(nv[i][3] - M[i]);
        s[i] = (e0 + e1) + (e2 + e3);
        if (last) { nv[i][0] = e0; nv[i][1] = e1; nv[i][2] = e2; nv[i][3] = e3; }
    }
    #pragma unroll
    for (int o = 16; o; o >>= 1)
        #pragma unroll
        for (int i = 0; i < 8; i++)
            s[i] += __shfl_xor_sync(0xffffffffu, s[i], o);
    if (lane == 0)
        #pragma unroll
        for (int i = 0; i < 8; i++) reds[i][wid] = s[i];
    __syncthreads();

    // phase 4: write
    #pragma unroll
    for (int i = 0; i < 8; i++) {
        float S = reds[i][0];
        #pragma unroll
        for (int wq = 1; wq < 8; wq++) S += reds[i][wq];
        float inv = 1.f / S;
        int row = rbase + i;
        if (last) {
            *(float4*)(outL + (size_t)row * N_ + tid * 4) =
                make_float4(nv[i][0] * inv, nv[i][1] * inv, nv[i][2] * inv, nv[i][3] * inv);
        } else {
            *(float4*)(g_Shat + (size_t)row * N_ + tid * 4) =
                make_float4(nv[i][0], nv[i][1], nv[i][2], nv[i][3]);
            if (tid == 0) { g_rowmax[row] = M[i]; g_rowinv[row] = inv; }
        }
    }
}

// ---------------- launcher ----------------
extern "C" void kernel_launch(void* const* d_in, const int* in_sizes, int n_in,
                              void* d_out, int out_size) {
    const float* x_s = (const float*)d_in[0];
    const int*   eis = (const int*)d_in[1];
    const float* x_t = (const float*)d_in[2];
    const int*   eit = (const int*)d_in[3];
    const float* W1s = (const float*)d_in[4];
    const float* W1n = (const float*)d_in[5];
    const float* b1  = (const float*)d_in[6];
    const float* W2s = (const float*)d_in[7];
    const float* W2n = (const float*)d_in[8];
    const float* b2  = (const float*)d_in[9];
    const float* Wm1 = (const float*)d_in[10];
    const float* bm1 = (const float*)d_in[11];
    const float* Wm2 = (const float*)d_in[12];
    const float* bm2 = (const float*)d_in[13];
    const float* rsteps = (const float*)d_in[14];
    float* out = (float*)d_out;

    void* p_agg1 = nullptr;
    cudaGetSymbolAddress(&p_agg1, g_agg1);

    cudaMemsetAsync(p_agg1, 0, sizeof(float) * 2 * BN_ * F_);
    k_agg1<<<dim3(E_ * 32 / 256, 2), 256>>>(x_s, eis, x_t, eit);
    k_psi1<<<dim3(BN_ / 64, 2), 256>>>(x_s, x_t, W1s, W1n, b1);
    k_shat<<<dim3(8, 8, 4), 256>>>();
    k_softmax_row<<<1024 + 192, 256>>>(out);   // + zero tail for step 0

    for (int i = 0; i < 2; i++) {
        const float* rs = rsteps + (size_t)i * BN_ * R_;
        k_rt<<<dim3(8, 8, 4), 256>>>(rs);
        k_agg2<<<dim3(E_ * 4 / 256, 2), 256>>>(rs, eis, eit);
        k_node2<<<dim3(BN_ / 64, 2), 256>>>(rs, W2s, W2n, b2, Wm1, bm1);
        int grid_u = (i == 0) ? (512 + 192) : 512;   // step-0 tail zeroes for step 1
        k_update<<<grid_u, 256>>>(Wm2, bm2, (i == 1) ? 1 : 0, out + (size_t)B_ * N_ * N_);
    }
}